// round 2
// baseline (speedup 1.0000x reference)
#include <cuda_runtime.h>
#include <cstdint>

#define TOKENS    2048
#define IN_DIM    1024
#define OUT_DIM   512
#define RANK      32
#define NTG       32      // T*G
#define NCELL     128     // T*G*K
#define TILE_TOK  128
#define OUT_CHUNK 64
#define ACC_STRIDE 68     // 64 + 4 pad (bank spread)

typedef unsigned long long u64;

// ---------------- scratch (static device globals: allocation-free) ----------
__device__ __align__(16) float         g_z[TOKENS * RANK];
__device__ __align__(16) unsigned char g_win[TOKENS * NTG];

// ---------------- helpers ----------------------------------------------------
__device__ __forceinline__ u64 dup2(float v) {
    u64 r; asm("mov.b64 %0, {%1, %1};" : "=l"(r) : "f"(v)); return r;
}
__device__ __forceinline__ void ffma2(u64& d, u64 a, u64 b) {
    asm("fma.rn.f32x2 %0, %1, %2, %0;" : "+l"(d) : "l"(a), "l"(b));
}
__device__ __forceinline__ float2 u2f(u64 v) {
    float2 r; asm("mov.b64 {%0, %1}, %2;" : "=f"(r.x), "=f"(r.y) : "l"(v)); return r;
}

// =============================================================================
// Kernel 1: z projection + routing argmin.  512 blocks x 256 thr, 4 tokens/blk.
// =============================================================================
__global__ __launch_bounds__(256) void kRoute(
    const float* __restrict__ x, const float* __restrict__ proj_w,
    const float* __restrict__ router_w, const float* __restrict__ router_b) {
    __shared__ __align__(16) float xs[4][IN_DIM];   // 16 KB
    __shared__ float zs[4][RANK];

    const int tid  = threadIdx.x;
    const int tok0 = blockIdx.x * 4;

    // stage 4 token rows of x (coalesced float4)
    {
        const float4* xg  = (const float4*)(x + (size_t)tok0 * IN_DIM);
        float4*       xs4 = (float4*)xs;
#pragma unroll
        for (int i = 0; i < 4; i++) xs4[tid + 256 * i] = xg[tid + 256 * i];
    }
    __syncthreads();

    const int w = tid >> 5, lane = tid & 31;
    // warp w computes z rows r = w*4+j for all 4 tokens
    float acc[4][4];   // [j][t]
#pragma unroll
    for (int j = 0; j < 4; j++)
#pragma unroll
        for (int t = 0; t < 4; t++) acc[j][t] = 0.f;

#pragma unroll 8
    for (int m = 0; m < 32; m++) {
        const int i = lane + 32 * m;
        float wv[4];
#pragma unroll
        for (int j = 0; j < 4; j++)
            wv[j] = __ldg(&proj_w[(size_t)(w * 4 + j) * IN_DIM + i]);
#pragma unroll
        for (int t = 0; t < 4; t++) {
            const float xv = xs[t][i];
#pragma unroll
            for (int j = 0; j < 4; j++) acc[j][t] += wv[j] * xv;
        }
    }
#pragma unroll
    for (int j = 0; j < 4; j++)
#pragma unroll
        for (int t = 0; t < 4; t++) {
            float s = acc[j][t];
#pragma unroll
            for (int off = 16; off > 0; off >>= 1)
                s += __shfl_xor_sync(0xffffffffu, s, off);
            if (lane == 0) {
                zs[t][w * 4 + j] = s;
                g_z[(size_t)(tok0 + t) * RANK + w * 4 + j] = s;
            }
        }
    __syncthreads();

    // scores in double; thread = (token t, tg).  argmin -> winner k (first min).
    if (tid < 128) {
        const int t  = tid >> 5;
        const int tg = tid & 31;
        const float* rw = router_w + (size_t)tg * 4 * RANK;
        const float* rb = router_b + (size_t)tg * 4;
        double s[4];
#pragma unroll
        for (int k = 0; k < 4; k++) s[k] = (double)rb[k];
#pragma unroll 8
        for (int r = 0; r < RANK; r++) {
            const double zr = (double)zs[t][r];
#pragma unroll
            for (int k = 0; k < 4; k++)
                s[k] += zr * (double)rw[k * RANK + r];
        }
        int best = 0; double bv = s[0];
#pragma unroll
        for (int k = 1; k < 4; k++)
            if (s[k] < bv) { bv = s[k]; best = k; }
        g_win[(size_t)(tok0 + t) * NTG + tg] = (unsigned char)best;
    }
}

// =============================================================================
// Kernel 2: selected affine apply.  grid (16 token tiles, 8 out chunks).
// Per block: cell loop with compact token lists, smem accumulation, no atomics.
// =============================================================================
// dynamic smem layout (bytes):
//   zdup   [32][128] u64          : 0      .. 32768
//   wtile64[2][32][32] u64        : 32768  .. 49152
//   acc    [128][68] float        : 49152  .. 83968
//   brow   [2][64] float          : 83968  .. 84480
//   win_s  [128][32] uchar        : 84480  .. 88576
//   lists  [2][128] short         : 88576  .. 89088
//   cnt    [128] int              : 89088  .. 89600
#define SMEM_APPLY 89600

__global__ __launch_bounds__(256) void kApply(
    const float* __restrict__ aw, const float* __restrict__ ab,
    float* __restrict__ out) {
    extern __shared__ __align__(16) unsigned char smem[];
    u64*           zdup   = (u64*)(smem);                  // [r*128 + tok]
    u64*           wtile  = (u64*)(smem + 32768);          // [buf*1024 + r*32 + j]
    float*         acc    = (float*)(smem + 49152);        // [tok*68 + o]
    float*         brow   = (float*)(smem + 83968);        // [buf*64 + o]
    unsigned char* win_s  = (unsigned char*)(smem + 84480);
    short*         lists  = (short*)(smem + 88576);        // [buf*128 + slot]
    int*           cnt    = (int*)(smem + 89088);

    const int tid   = threadIdx.x;
    const int lane  = tid & 31;
    const int tile0 = blockIdx.x * TILE_TOK;
    const int oc    = blockIdx.y * OUT_CHUNK;
    const int q     = tid >> 4;   // 0..15 out quad
    const int sl    = tid & 15;   // slot-pair id

    // ---- prologue staging ----
    // win bytes: 4 KB
    ((uint4*)win_s)[tid] = ((const uint4*)(g_win + (size_t)tile0 * NTG))[tid];
    // zdup: coalesced float4 loads, duplicated u64 stores
    for (int e = tid; e < TILE_TOK * RANK / 4; e += 256) {
        const int tk = e >> 3, r4 = e & 7;
        float4 v = ((const float4*)(g_z + (size_t)(tile0 + tk) * RANK))[r4];
        zdup[(r4 * 4 + 0) * TILE_TOK + tk] = dup2(v.x);
        zdup[(r4 * 4 + 1) * TILE_TOK + tk] = dup2(v.y);
        zdup[(r4 * 4 + 2) * TILE_TOK + tk] = dup2(v.z);
        zdup[(r4 * 4 + 3) * TILE_TOK + tk] = dup2(v.w);
    }
    // zero acc + counters
    for (int e = tid; e < TILE_TOK * ACC_STRIDE; e += 256) acc[e] = 0.f;
    if (tid < NCELL) cnt[tid] = 0;

    // stage cell 0 tile + build list 0
    {
        float* wt = (float*)wtile;                 // buf 0
#pragma unroll
        for (int v = tid; v < 512; v += 256) {
            const int r = v >> 4, o4 = v & 15;
            ((float4*)&wt[r * 64])[o4] =
                ((const float4*)(aw + ((size_t)0 * RANK + r) * OUT_DIM + oc))[o4];
        }
        if (tid < 16)
            ((float4*)brow)[tid] = ((const float4*)(ab + oc))[tid];
        if (tid < 128) {
            const bool sel = (win_s[tid * NTG + 0] == 0);   // cell 0: tg=0,k=0
            const unsigned mask = __ballot_sync(0xffffffffu, sel);
            int base = 0;
            if (lane == 0) base = atomicAdd(&cnt[0], __popc(mask));
            base = __shfl_sync(0xffffffffu, base, 0);
            if (sel) lists[base + __popc(mask & ((1u << lane) - 1u))] = (short)tid;
        }
    }
    __syncthreads();

    // ---- main cell loop: one sync per cell (double-buffered wtile/lists) ----
    for (int c = 0; c < NCELL; c++) {
        const int buf = c & 1;
        // stage next cell + build next list (writes go to buf^1 / cnt[c+1])
        if (c + 1 < NCELL) {
            const int cn = c + 1, bn = buf ^ 1;
            float* wt = (float*)(wtile + bn * 1024);
#pragma unroll
            for (int v = tid; v < 512; v += 256) {
                const int r = v >> 4, o4 = v & 15;
                ((float4*)&wt[r * 64])[o4] =
                    ((const float4*)(aw + ((size_t)cn * RANK + r) * OUT_DIM + oc))[o4];
            }
            if (tid < 16)
                ((float4*)(brow + bn * 64))[tid] =
                    ((const float4*)(ab + (size_t)cn * OUT_DIM + oc))[tid];
            if (tid < 128) {
                const int tg = cn >> 2, k = cn & 3;
                const bool sel = (win_s[tid * NTG + tg] == k);
                const unsigned mask = __ballot_sync(0xffffffffu, sel);
                int base = 0;
                if (lane == 0) base = atomicAdd(&cnt[cn], __popc(mask));
                base = __shfl_sync(0xffffffffu, base, 0);
                if (sel)
                    lists[bn * 128 + base + __popc(mask & ((1u << lane) - 1u))] =
                        (short)tid;
            }
        }

        // compute current cell
        const int     n   = cnt[c];
        const short*  lst = lists + buf * 128;
        const u64*    wp  = wtile + buf * 1024 + q * 2;
        const u64     b01 = *(const u64*)&brow[buf * 64 + q * 4];
        const u64     b23 = *(const u64*)&brow[buf * 64 + q * 4 + 2];
        for (int b0 = 0; b0 < n; b0 += 32) {
            const int s0 = b0 + 2 * sl, s1 = s0 + 1;
            if (s0 < n) {
                const int ta = lst[s0];
                const int tb = (s1 < n) ? lst[s1] : ta;
                u64 a01 = b01, a23 = b23, c01 = b01, c23 = b23;
                const u64* za = zdup + ta;
                const u64* zb = zdup + tb;
#pragma unroll
                for (int r = 0; r < RANK; r++) {
                    const u64 z1  = za[r * TILE_TOK];
                    const u64 z2  = zb[r * TILE_TOK];
                    const u64 w01 = wp[r * 32];
                    const u64 w23 = wp[r * 32 + 1];
                    ffma2(a01, z1, w01);
                    ffma2(a23, z1, w23);
                    ffma2(c01, z2, w01);
                    ffma2(c23, z2, w23);
                }
                {   // RMW acc for token a
                    float4* pa = (float4*)&acc[ta * ACC_STRIDE + q * 4];
                    float4 cur = *pa;
                    const float2 lo = u2f(a01), hi = u2f(a23);
                    cur.x += lo.x; cur.y += lo.y; cur.z += hi.x; cur.w += hi.y;
                    *pa = cur;
                }
                if (s1 < n) {   // RMW acc for token b
                    float4* pb = (float4*)&acc[tb * ACC_STRIDE + q * 4];
                    float4 cur = *pb;
                    const float2 lo = u2f(c01), hi = u2f(c23);
                    cur.x += lo.x; cur.y += lo.y; cur.z += hi.x; cur.w += hi.y;
                    *pb = cur;
                }
            }
        }
        __syncthreads();
    }

    // ---- epilogue: scale + exclusive store ----
    const float SCALE = 0.17677669529663687f;   // 1/sqrt(32)
    for (int e = tid; e < TILE_TOK * OUT_CHUNK / 4; e += 256) {
        const int tk = e >> 4, o4 = e & 15;
        float4 v = *(const float4*)&acc[tk * ACC_STRIDE + o4 * 4];
        v.x *= SCALE; v.y *= SCALE; v.z *= SCALE; v.w *= SCALE;
        ((float4*)(out + (size_t)(tile0 + tk) * OUT_DIM + oc))[o4] = v;
    }
}

// =============================================================================
extern "C" void kernel_launch(void* const* d_in, const int* in_sizes, int n_in,
                              void* d_out, int out_size) {
    const float* x   = (const float*)d_in[0];
    const float* pw  = (const float*)d_in[1];
    const float* rw  = (const float*)d_in[2];
    const float* rb  = (const float*)d_in[3];
    const float* aw  = (const float*)d_in[4];
    const float* ab  = (const float*)d_in[5];
    float*       out = (float*)d_out;

    cudaFuncSetAttribute(kApply, cudaFuncAttributeMaxDynamicSharedMemorySize,
                         SMEM_APPLY);

    kRoute<<<TOKENS / 4, 256>>>(x, pw, rw, rb);
    kApply<<<dim3(TOKENS / TILE_TOK, OUT_DIM / OUT_CHUNK), 256, SMEM_APPLY>>>(
        aw, ab, out);
}

// round 3
// speedup vs baseline: 1.9362x; 1.9362x over previous
#include <cuda_runtime.h>
#include <cstdint>

typedef unsigned long long u64;

#define TOKENS   2048
#define IN_DIM   1024
#define OUT_DIM  512
#define RANK     32
#define NTG      32        // T*G
#define NCELL    128
#define TILE_TOK 128
#define OC       32        // outputs per block
#define CELLF    1060      // floats per staged cell tile: 33 rows x 32 + 4 pad
#define BUFF     (4*CELLF) // one tg buffer (4 cells) in floats

// ---------------- scratch (static device globals: allocation-free) ----------
__device__ __align__(16) float         g_z[TOKENS * RANK];
__device__ __align__(16) unsigned char g_win[TOKENS * NTG];

// ---------------- helpers ----------------------------------------------------
__device__ __forceinline__ u64 dup2(float v) {
    u64 r; asm("mov.b64 %0, {%1, %1};" : "=l"(r) : "f"(v)); return r;
}
__device__ __forceinline__ void ffma2(u64& d, u64 a, u64 b) {
    asm("fma.rn.f32x2 %0, %1, %2, %0;" : "+l"(d) : "l"(a), "l"(b));
}
__device__ __forceinline__ float2 u2f(u64 v) {
    float2 r; asm("mov.b64 {%0, %1}, %2;" : "=f"(r.x), "=f"(r.y) : "l"(v)); return r;
}

// =============================================================================
// Kernel 1: z projection + routing argmin.  512 blocks x 256 thr, 4 tokens/blk.
// =============================================================================
__global__ __launch_bounds__(256) void kRoute(
    const float* __restrict__ x, const float* __restrict__ proj_w,
    const float* __restrict__ router_w, const float* __restrict__ router_b) {
    __shared__ __align__(16) float xs[4][IN_DIM];   // 16 KB
    __shared__ float zs[4][RANK];

    const int tid  = threadIdx.x;
    const int tok0 = blockIdx.x * 4;

    {   // stage 4 token rows of x (coalesced float4)
        const float4* xg  = (const float4*)(x + (size_t)tok0 * IN_DIM);
        float4*       xs4 = (float4*)xs;
#pragma unroll
        for (int i = 0; i < 4; i++) xs4[tid + 256 * i] = xg[tid + 256 * i];
    }
    __syncthreads();

    const int w = tid >> 5, lane = tid & 31;
    float acc[4][4];   // [j][t]
#pragma unroll
    for (int j = 0; j < 4; j++)
#pragma unroll
        for (int t = 0; t < 4; t++) acc[j][t] = 0.f;

#pragma unroll 8
    for (int m = 0; m < 32; m++) {
        const int i = lane + 32 * m;
        float wv[4];
#pragma unroll
        for (int j = 0; j < 4; j++)
            wv[j] = __ldg(&proj_w[(size_t)(w * 4 + j) * IN_DIM + i]);
#pragma unroll
        for (int t = 0; t < 4; t++) {
            const float xv = xs[t][i];
#pragma unroll
            for (int j = 0; j < 4; j++) acc[j][t] += wv[j] * xv;
        }
    }
#pragma unroll
    for (int j = 0; j < 4; j++)
#pragma unroll
        for (int t = 0; t < 4; t++) {
            float s = acc[j][t];
#pragma unroll
            for (int off = 16; off > 0; off >>= 1)
                s += __shfl_xor_sync(0xffffffffu, s, off);
            if (lane == 0) {
                zs[t][w * 4 + j] = s;
                g_z[(size_t)(tok0 + t) * RANK + w * 4 + j] = s;
            }
        }
    __syncthreads();

    // scores (fp32); thread = (token t, tg). first-min argmin -> winner k.
    if (tid < 128) {
        const int t  = tid >> 5;
        const int tg = tid & 31;
        const float* rw = router_w + (size_t)tg * 4 * RANK;
        const float* rb = router_b + (size_t)tg * 4;
        float s[4];
#pragma unroll
        for (int k = 0; k < 4; k++) s[k] = rb[k];
#pragma unroll 8
        for (int r = 0; r < RANK; r++) {
            const float zr = zs[t][r];
#pragma unroll
            for (int k = 0; k < 4; k++)
                s[k] += zr * rw[k * RANK + r];
        }
        int best = 0; float bv = s[0];
#pragma unroll
        for (int k = 1; k < 4; k++)
            if (s[k] < bv) { bv = s[k]; best = k; }
        g_win[(size_t)(tok0 + t) * NTG + tg] = (unsigned char)best;
    }
}

// =============================================================================
// Kernel 2: selected affine apply.
// Grid (16 token tiles, 16 out-chunks of 32) x 128 threads.
// Lane owns 1 token x 32 outs; acc (16 u64) and z (33 f32) live in registers
// for the whole kernel. Per tg: cp.async-stage 4 cell tiles (bias folded as
// row 32), each lane streams its winner cell's weights.
// =============================================================================
__device__ __forceinline__ void stage_tg(
    const float* __restrict__ aw, const float* __restrict__ ab,
    int oc, int tg, int buf, int tid, uint32_t wt0) {
    const int c0 = tg * 4;
    for (int s = tid; s < 4 * 33 * 8; s += 128) {
        const int c   = s / 264;
        const int rem = s - c * 264;
        const int r   = rem >> 3, j = rem & 7;
        const float* src = (r < 32)
            ? aw + (((size_t)(c0 + c) * RANK + r) * OUT_DIM + oc + j * 4)
            : ab + ((size_t)(c0 + c) * OUT_DIM + oc + j * 4);
        const uint32_t dst =
            wt0 + (uint32_t)((buf * BUFF + c * CELLF + r * 32 + j * 4) * 4);
        asm volatile("cp.async.ca.shared.global [%0], [%1], 16;"
                     :: "r"(dst), "l"(src));
    }
    asm volatile("cp.async.commit_group;" ::: "memory");
}

__global__ __launch_bounds__(128) void kApply(
    const float* __restrict__ aw, const float* __restrict__ ab,
    float* __restrict__ out) {
    __shared__ __align__(16) float wt[2 * BUFF];   // 33.9 KB
    const int tid = threadIdx.x;
    const int t   = blockIdx.x * TILE_TOK + tid;   // this lane's token
    const int oc  = blockIdx.y * OC;
    const uint32_t wt0 = (uint32_t)__cvta_generic_to_shared(wt);

    // z into registers (once), z[32] = 1 pairs with the bias row
    float zr[33];
    {
        const float4* zp = (const float4*)(g_z + (size_t)t * RANK);
#pragma unroll
        for (int j = 0; j < 8; j++) {
            float4 v = __ldg(zp + j);
            zr[4 * j] = v.x; zr[4 * j + 1] = v.y;
            zr[4 * j + 2] = v.z; zr[4 * j + 3] = v.w;
        }
        zr[32] = 1.0f;
    }

    u64 acc[16];
#pragma unroll
    for (int i = 0; i < 16; i++) acc[i] = 0ull;

    const unsigned char* winp = g_win + (size_t)t * NTG;

    stage_tg(aw, ab, oc, 0, 0, tid, wt0);

    for (int tg = 0; tg < NTG; tg++) {
        if (tg + 1 < NTG) {
            stage_tg(aw, ab, oc, tg + 1, (tg + 1) & 1, tid, wt0);
            asm volatile("cp.async.wait_group 1;" ::: "memory");
        } else {
            asm volatile("cp.async.wait_group 0;" ::: "memory");
        }
        __syncthreads();

        const int cell = winp[tg];
        const uint32_t base =
            wt0 + (uint32_t)(((tg & 1) * BUFF + cell * CELLF) * 4);
#pragma unroll
        for (int r = 0; r < 33; r++) {
            const u64 zd = dup2(zr[r]);
#pragma unroll
            for (int j = 0; j < 8; j++) {
                u64 w01, w23;
                asm("ld.shared.v2.b64 {%0, %1}, [%2];"
                    : "=l"(w01), "=l"(w23)
                    : "r"(base + (uint32_t)(r * 128 + j * 16)));
                ffma2(acc[2 * j],     zd, w01);
                ffma2(acc[2 * j + 1], zd, w23);
            }
        }
        __syncthreads();   // compute done before next iteration re-stages buf
    }

    // epilogue: scale + store (each (t, oc-range) owned exclusively)
    const float S = 0.17677669529663687f;   // 1/sqrt(32)
    float* op = out + (size_t)t * OUT_DIM + oc;
#pragma unroll
    for (int j = 0; j < 8; j++) {
        const float2 a = u2f(acc[2 * j]), b = u2f(acc[2 * j + 1]);
        float4 v;
        v.x = a.x * S; v.y = a.y * S; v.z = b.x * S; v.w = b.y * S;
        ((float4*)op)[j] = v;
    }
}

// =============================================================================
extern "C" void kernel_launch(void* const* d_in, const int* in_sizes, int n_in,
                              void* d_out, int out_size) {
    const float* x   = (const float*)d_in[0];
    const float* pw  = (const float*)d_in[1];
    const float* rw  = (const float*)d_in[2];
    const float* rb  = (const float*)d_in[3];
    const float* aw  = (const float*)d_in[4];
    const float* ab  = (const float*)d_in[5];
    float*       out = (float*)d_out;

    kRoute<<<TOKENS / 4, 256>>>(x, pw, rw, rb);
    kApply<<<dim3(TOKENS / TILE_TOK, OUT_DIM / OC), 128>>>(aw, ab, out);
}